// round 1
// baseline (speedup 1.0000x reference)
#include <cuda_runtime.h>
#include <cuda_bf16.h>
#include <cstddef>

// Problem constants
#define BATCH   2
#define SEQ     2048
#define DIM     1024
#define HEADS   16
#define DHEAD   64
#define INNER   1024          // HEADS*DHEAD
#define ROWS    (BATCH*SEQ)   // 4096
#define QKV_N   (3*INNER)     // 3072
#define EPS     1e-5f
#define QSCALE  0.125f        // DHEAD^-0.5

// ---------------- scratch (static device globals; no runtime allocation) ----
__device__ float g_xn  [ (size_t)ROWS * DIM   ];   // 16 MB
__device__ float g_qkv [ (size_t)ROWS * QKV_N ];   // 48 MB
__device__ float g_att [ (size_t)ROWS * INNER ];   // 16 MB
__device__ float g_proj[ (size_t)ROWS * DIM   ];   // 16 MB

// ---------------- LayerNorm (one row per block, 256 thr, 4 floats/thr) -----
__device__ __forceinline__ void ln_body(const float* __restrict__ in,
                                        const float* __restrict__ gamma,
                                        const float* __restrict__ beta,
                                        float* __restrict__ out)
{
    const int row = blockIdx.x;
    const float* xr = in + (size_t)row * DIM;
    const int t = threadIdx.x;

    float4 xv = *(const float4*)(xr + t * 4);
    float sum = xv.x + xv.y + xv.z + xv.w;
    float sq  = xv.x*xv.x + xv.y*xv.y + xv.z*xv.z + xv.w*xv.w;

    #pragma unroll
    for (int o = 16; o > 0; o >>= 1) {
        sum += __shfl_xor_sync(0xffffffffu, sum, o);
        sq  += __shfl_xor_sync(0xffffffffu, sq,  o);
    }
    __shared__ float s1[8], s2[8];
    const int warp = t >> 5;
    if ((t & 31) == 0) { s1[warp] = sum; s2[warp] = sq; }
    __syncthreads();
    float tot = 0.f, totq = 0.f;
    #pragma unroll
    for (int w = 0; w < 8; w++) { tot += s1[w]; totq += s2[w]; }

    const float mean = tot * (1.0f / DIM);
    const float var  = totq * (1.0f / DIM) - mean * mean;
    const float inv  = rsqrtf(var + EPS);

    float4 gv = *(const float4*)(gamma + t * 4);
    float4 bv = *(const float4*)(beta  + t * 4);
    float4 ov;
    ov.x = (xv.x - mean) * inv * gv.x + bv.x;
    ov.y = (xv.y - mean) * inv * gv.y + bv.y;
    ov.z = (xv.z - mean) * inv * gv.z + bv.z;
    ov.w = (xv.w - mean) * inv * gv.w + bv.w;
    *(float4*)(out + (size_t)row * DIM + t * 4) = ov;
}

__global__ __launch_bounds__(256) void ln1_kernel(const float* __restrict__ x,
                                                  const float* __restrict__ g,
                                                  const float* __restrict__ b)
{ ln_body(x, g, b, g_xn); }

__global__ __launch_bounds__(256) void ln2_kernel(const float* __restrict__ g,
                                                  const float* __restrict__ b,
                                                  float* __restrict__ out)
{ ln_body(g_proj, g, b, out); }

// ---------------- fp32 tiled GEMM:  C[M,N] = A[M,K] * B[K,N] ----------------
// BM=128, BN=64, BK=16, 256 threads, each thread computes 8x4.
template<int M, int N, int K>
__device__ __forceinline__ void gemm_body(const float* __restrict__ A,
                                          const float* __restrict__ B,
                                          float* __restrict__ C)
{
    constexpr int BM = 128, BN = 64, BK = 16;
    __shared__ float As[BK][132];   // [k][m], padded (132*4 = 528B, 16B aligned)
    __shared__ float Bs[BK][68];    // [k][n], padded (272B rows)

    const int tid = threadIdx.x;
    const int tx = tid & 15;        // 0..15 -> n
    const int ty = tid >> 4;        // 0..15 -> m
    const int bm = blockIdx.y * BM;
    const int bn = blockIdx.x * BN;

    float acc[8][4];
    #pragma unroll
    for (int i = 0; i < 8; i++)
        #pragma unroll
        for (int j = 0; j < 4; j++) acc[i][j] = 0.f;

    for (int k0 = 0; k0 < K; k0 += BK) {
        // A tile: 128x16 floats = 512 float4; 2 per thread; stored transposed
        #pragma unroll
        for (int tldr = 0; tldr < 2; tldr++) {
            int idx = tid + tldr * 256;       // 0..511
            int row = idx >> 2;
            int c4  = (idx & 3) * 4;
            float4 v = *(const float4*)(A + (size_t)(bm + row) * K + k0 + c4);
            As[c4 + 0][row] = v.x;
            As[c4 + 1][row] = v.y;
            As[c4 + 2][row] = v.z;
            As[c4 + 3][row] = v.w;
        }
        // B tile: 16x64 floats = 256 float4; 1 per thread
        {
            int row = tid >> 4;
            int c4  = (tid & 15) * 4;
            float4 v = *(const float4*)(B + (size_t)(k0 + row) * N + bn + c4);
            *(float4*)&Bs[row][c4] = v;
        }
        __syncthreads();

        #pragma unroll
        for (int kk = 0; kk < BK; kk++) {
            float4 a0 = *(const float4*)&As[kk][ty * 8];
            float4 a1 = *(const float4*)&As[kk][ty * 8 + 4];
            float4 b0 = *(const float4*)&Bs[kk][tx * 4];
            float a[8] = {a0.x,a0.y,a0.z,a0.w,a1.x,a1.y,a1.z,a1.w};
            float bb[4] = {b0.x,b0.y,b0.z,b0.w};
            #pragma unroll
            for (int i = 0; i < 8; i++)
                #pragma unroll
                for (int j = 0; j < 4; j++)
                    acc[i][j] = fmaf(a[i], bb[j], acc[i][j]);
        }
        __syncthreads();
    }

    #pragma unroll
    for (int i = 0; i < 8; i++) {
        float4 v = {acc[i][0], acc[i][1], acc[i][2], acc[i][3]};
        *(float4*)(C + (size_t)(bm + ty * 8 + i) * N + bn + tx * 4) = v;
    }
}

__global__ __launch_bounds__(256) void gemm_qkv_kernel(const float* __restrict__ w)
{ gemm_body<ROWS, QKV_N, DIM>(g_xn, w, g_qkv); }

__global__ __launch_bounds__(256) void gemm_out_kernel(const float* __restrict__ w)
{ gemm_body<ROWS, DIM, INNER>(g_att, w, g_proj); }

// ---------------- causal ReLU attention (no softmax => pure streaming) ------
// Block: 64 query rows of one (b,h). Loop over key tiles j<=i:
//   S = (Q*scale) K^T ; S = causal_relu(S) ; O += S V
// smem tiles stride 65 (scalar LDS, conflict-light).
#define TPAD 65
#define ATTN_SMEM (3 * 64 * TPAD * 4)

__global__ __launch_bounds__(256) void attn_kernel()
{
    extern __shared__ float sm[];
    float* Qs = sm;                   // 64 x 65
    float* Ks = sm + 64 * TPAD;       // 64 x 65 (reused for V)
    float* Ss = sm + 2 * 64 * TPAD;   // 64 x 65

    const int tid = threadIdx.x;
    const int tx = tid & 15;          // key/dhead tile col group
    const int ty = tid >> 4;          // query row group

    const int qt = blockIdx.x;        // 0..31 query tile
    const int bh = blockIdx.y;        // 0..31
    const int b  = bh >> 4;
    const int h  = bh & 15;

    const float* qb = g_qkv + (size_t)b * SEQ * QKV_N + h * DHEAD;
    const float* kb = qb + INNER;
    const float* vb = qb + 2 * INNER;
    const int qi0 = qt * 64;

    // load Q tile (scaled)
    #pragma unroll
    for (int t = 0; t < 4; t++) {
        int idx = tid + t * 256;            // 0..1023
        int row = idx >> 4;
        int c4  = (idx & 15) * 4;
        float4 v = *(const float4*)(qb + (size_t)(qi0 + row) * QKV_N + c4);
        float* dst = &Qs[row * TPAD + c4];
        dst[0] = v.x * QSCALE; dst[1] = v.y * QSCALE;
        dst[2] = v.z * QSCALE; dst[3] = v.w * QSCALE;
    }

    float o[4][4];
    #pragma unroll
    for (int i = 0; i < 4; i++)
        #pragma unroll
        for (int d = 0; d < 4; d++) o[i][d] = 0.f;

    for (int kt = 0; kt <= qt; kt++) {
        __syncthreads();   // Ks free (prev O done) / Q visible
        // load K tile
        #pragma unroll
        for (int t = 0; t < 4; t++) {
            int idx = tid + t * 256;
            int row = idx >> 4;
            int c4  = (idx & 15) * 4;
            float4 v = *(const float4*)(kb + (size_t)(kt * 64 + row) * QKV_N + c4);
            float* dst = &Ks[row * TPAD + c4];
            dst[0] = v.x; dst[1] = v.y; dst[2] = v.z; dst[3] = v.w;
        }
        __syncthreads();

        // S = Q K^T (4x4 fragment per thread)
        float s[4][4];
        #pragma unroll
        for (int i = 0; i < 4; i++)
            #pragma unroll
            for (int j = 0; j < 4; j++) s[i][j] = 0.f;

        #pragma unroll 4
        for (int d = 0; d < DHEAD; d++) {
            float qv[4], kv[4];
            #pragma unroll
            for (int i = 0; i < 4; i++) qv[i] = Qs[(ty * 4 + i) * TPAD + d];
            #pragma unroll
            for (int j = 0; j < 4; j++) kv[j] = Ks[(tx * 4 + j) * TPAD + d];
            #pragma unroll
            for (int i = 0; i < 4; i++)
                #pragma unroll
                for (int j = 0; j < 4; j++)
                    s[i][j] = fmaf(qv[i], kv[j], s[i][j]);
        }

        // causal relu + stage to smem
        #pragma unroll
        for (int i = 0; i < 4; i++) {
            int gi = qi0 + ty * 4 + i;
            #pragma unroll
            for (int j = 0; j < 4; j++) {
                int gj = kt * 64 + tx * 4 + j;
                float v = (gj <= gi) ? fmaxf(s[i][j], 0.f) : 0.f;
                Ss[(ty * 4 + i) * TPAD + tx * 4 + j] = v;
            }
        }
        __syncthreads();

        // load V tile into Ks
        #pragma unroll
        for (int t = 0; t < 4; t++) {
            int idx = tid + t * 256;
            int row = idx >> 4;
            int c4  = (idx & 15) * 4;
            float4 v = *(const float4*)(vb + (size_t)(kt * 64 + row) * QKV_N + c4);
            float* dst = &Ks[row * TPAD + c4];
            dst[0] = v.x; dst[1] = v.y; dst[2] = v.z; dst[3] = v.w;
        }
        __syncthreads();

        // O += S V
        #pragma unroll 4
        for (int j = 0; j < 64; j++) {
            float sv[4], vv[4];
            #pragma unroll
            for (int i = 0; i < 4; i++) sv[i] = Ss[(ty * 4 + i) * TPAD + j];
            #pragma unroll
            for (int d = 0; d < 4; d++) vv[d] = Ks[j * TPAD + tx * 4 + d];
            #pragma unroll
            for (int i = 0; i < 4; i++)
                #pragma unroll
                for (int d = 0; d < 4; d++)
                    o[i][d] = fmaf(sv[i], vv[d], o[i][d]);
        }
    }

    // store O into [rows, h*64+d] layout
    float* ob = g_att + (size_t)(b * SEQ + qi0) * INNER + h * DHEAD;
    #pragma unroll
    for (int i = 0; i < 4; i++) {
        float4 v = {o[i][0], o[i][1], o[i][2], o[i][3]};
        *(float4*)(ob + (size_t)(ty * 4 + i) * INNER + tx * 4) = v;
    }
}

// ---------------- launch ----------------------------------------------------
extern "C" void kernel_launch(void* const* d_in, const int* in_sizes, int n_in,
                              void* d_out, int out_size)
{
    const float* x     = (const float*)d_in[0];
    const float* ln1_g = (const float*)d_in[1];
    const float* ln1_b = (const float*)d_in[2];
    const float* w_qkv = (const float*)d_in[3];
    const float* w_out = (const float*)d_in[4];
    const float* ln2_g = (const float*)d_in[5];
    const float* ln2_b = (const float*)d_in[6];
    float* out = (float*)d_out;

    cudaFuncSetAttribute(attn_kernel,
                         cudaFuncAttributeMaxDynamicSharedMemorySize, ATTN_SMEM);

    ln1_kernel<<<ROWS, 256>>>(x, ln1_g, ln1_b);
    gemm_qkv_kernel<<<dim3(QKV_N / 64, ROWS / 128), 256>>>(w_qkv);
    attn_kernel<<<dim3(SEQ / 64, BATCH * HEADS), 256, ATTN_SMEM>>>();
    gemm_out_kernel<<<dim3(DIM / 64, ROWS / 128), 256>>>(w_out);
    ln2_kernel<<<ROWS, 256>>>(ln2_g, ln2_b, out);
}